// round 1
// baseline (speedup 1.0000x reference)
#include <cuda_runtime.h>
#include <cuda_bf16.h>
#include <math_constants.h>

// Problem constants
#define N_TOKENS   16384
#define DIM        2048
#define NEXP       64
#define NCOLS      128     // 64 gate + 64 noise
#define TOK_BLK    64
#define KTILE      32
#define NTHREADS   256
#define NBLOCKS    (N_TOKENS / TOK_BLK)   // 256

#define AS_STRIDE  68      // padded row stride (floats), 68*4 % 16 == 0
#define BS_STRIDE  132     // 132*4 % 16 == 0
#define AS_BUF     (KTILE * AS_STRIDE)    // 2176 floats
#define BS_BUF     (KTILE * BS_STRIDE)    // 4224 floats

// Epilogue smem layout (float offsets), overlaps GEMM buffers
#define LOGITS_OFF   0                    // [64][129]
#define LOGITS_STR   129
#define NOISE_OFF    (64 * 129)           // [64][65]
#define NOISE_STR    65
#define V2_OFF       (NOISE_OFF + 64 * 65)
#define V3_OFF       (V2_OFF + 64)
#define W1_OFF       (V3_OFF + 64)
#define W2_OFF       (W1_OFF + 64)
#define I1_OFF       (W2_OFF + 64)
#define I2_OFF       (I1_OFF + 64)
#define IMPP_OFF     (I2_OFF + 64)        // [4][64]
#define LOADP_OFF    (IMPP_OFF + 256)     // [4][64]
#define SMEM_FLOATS  (LOADP_OFF + 256)    // 13312 floats
#define SMEM_BYTES   (SMEM_FLOATS * 4)    // 53248 B (> GEMM region 51200 B)

#define EPS 1e-9f

// Deterministic per-block partials
__device__ float g_imp_part [NBLOCKS * NEXP];
__device__ float g_load_part[NBLOCKS * NEXP];

__global__ void __launch_bounds__(NTHREADS)
router_main_kernel(const float* __restrict__ x,
                   const float* __restrict__ noise,
                   const float* __restrict__ Wg,
                   const float* __restrict__ Wn,
                   float* __restrict__ out)
{
    extern __shared__ float sm[];
    float* As = sm;                      // [2][KTILE][AS_STRIDE]
    float* Bs = sm + 2 * AS_BUF;         // [2][KTILE][BS_STRIDE]

    const int tid = threadIdx.x;
    const int tx  = tid & 15;            // col group (8 cols)
    const int ty  = tid >> 4;            // row group (4 rows)
    const int tok0 = blockIdx.x * TOK_BLK;

    // ---------------- GEMM: C[64][128] = x_tile @ [Wg;Wn]^T ----------------
    // A loads: 2 float4/thread/chunk.  B loads: 4 float4/thread/chunk.
    const int idxA0 = tid,       rowA0 = idxA0 >> 3, kqA0 = idxA0 & 7;
    const int idxA1 = tid + 256, rowA1 = idxA1 >> 3, kqA1 = idxA1 & 7;
    const float* aSrc0 = x + (size_t)(tok0 + rowA0) * DIM + kqA0 * 4;
    const float* aSrc1 = x + (size_t)(tok0 + rowA1) * DIM + kqA1 * 4;

    const float* bSrc[4];
    int colB[4], kqB[4];
#pragma unroll
    for (int i = 0; i < 4; ++i) {
        int idx = tid + i * 256;
        colB[i] = idx >> 3;
        kqB[i]  = idx & 7;
        bSrc[i] = (colB[i] < NEXP)
                    ? (Wg + (size_t)colB[i] * DIM + kqB[i] * 4)
                    : (Wn + (size_t)(colB[i] - NEXP) * DIM + kqB[i] * 4);
    }

    float acc[4][8];
#pragma unroll
    for (int i = 0; i < 4; ++i)
#pragma unroll
        for (int j = 0; j < 8; ++j) acc[i][j] = 0.f;

    // prefetch chunk 0 and store to buffer 0
    float4 ra0 = *(const float4*)(aSrc0);
    float4 ra1 = *(const float4*)(aSrc1);
    float4 rb[4];
#pragma unroll
    for (int i = 0; i < 4; ++i) rb[i] = *(const float4*)(bSrc[i]);

    {
        float* d0 = &As[(kqA0 * 4) * AS_STRIDE + rowA0];
        d0[0] = ra0.x; d0[AS_STRIDE] = ra0.y; d0[2*AS_STRIDE] = ra0.z; d0[3*AS_STRIDE] = ra0.w;
        float* d1 = &As[(kqA1 * 4) * AS_STRIDE + rowA1];
        d1[0] = ra1.x; d1[AS_STRIDE] = ra1.y; d1[2*AS_STRIDE] = ra1.z; d1[3*AS_STRIDE] = ra1.w;
#pragma unroll
        for (int i = 0; i < 4; ++i) {
            float* db = &Bs[(kqB[i] * 4) * BS_STRIDE + colB[i]];
            db[0] = rb[i].x; db[BS_STRIDE] = rb[i].y; db[2*BS_STRIDE] = rb[i].z; db[3*BS_STRIDE] = rb[i].w;
        }
    }
    __syncthreads();

    const int NCHUNK = DIM / KTILE;   // 64
    for (int kt = 0; kt < NCHUNK; ++kt) {
        const int cur = kt & 1;
        const int nxt = cur ^ 1;
        if (kt < NCHUNK - 1) {
            const int off = (kt + 1) * KTILE;
            ra0 = *(const float4*)(aSrc0 + off);
            ra1 = *(const float4*)(aSrc1 + off);
#pragma unroll
            for (int i = 0; i < 4; ++i) rb[i] = *(const float4*)(bSrc[i] + off);
        }

        const float* Ab = &As[cur * AS_BUF];
        const float* Bb = &Bs[cur * BS_BUF];
#pragma unroll
        for (int kk = 0; kk < KTILE; ++kk) {
            float4 a  = *(const float4*)&Ab[kk * AS_STRIDE + ty * 4];
            float4 b0 = *(const float4*)&Bb[kk * BS_STRIDE + tx * 8];
            float4 b1 = *(const float4*)&Bb[kk * BS_STRIDE + tx * 8 + 4];
            float av[4] = {a.x, a.y, a.z, a.w};
            float bv[8] = {b0.x, b0.y, b0.z, b0.w, b1.x, b1.y, b1.z, b1.w};
#pragma unroll
            for (int i = 0; i < 4; ++i)
#pragma unroll
                for (int j = 0; j < 8; ++j)
                    acc[i][j] = fmaf(av[i], bv[j], acc[i][j]);
        }

        if (kt < NCHUNK - 1) {
            float* d0 = &As[nxt * AS_BUF + (kqA0 * 4) * AS_STRIDE + rowA0];
            d0[0] = ra0.x; d0[AS_STRIDE] = ra0.y; d0[2*AS_STRIDE] = ra0.z; d0[3*AS_STRIDE] = ra0.w;
            float* d1 = &As[nxt * AS_BUF + (kqA1 * 4) * AS_STRIDE + rowA1];
            d1[0] = ra1.x; d1[AS_STRIDE] = ra1.y; d1[2*AS_STRIDE] = ra1.z; d1[3*AS_STRIDE] = ra1.w;
#pragma unroll
            for (int i = 0; i < 4; ++i) {
                float* db = &Bs[nxt * BS_BUF + (kqB[i] * 4) * BS_STRIDE + colB[i]];
                db[0] = rb[i].x; db[BS_STRIDE] = rb[i].y; db[2*BS_STRIDE] = rb[i].z; db[3*BS_STRIDE] = rb[i].w;
            }
        }
        __syncthreads();
    }

    // ---------------- Epilogue (reuse smem) ----------------
    float* logits_s = sm + LOGITS_OFF;   // [64][129]: cols 0-63 gate logits, 64-127 noise logits (then std)
    float* noise_s  = sm + NOISE_OFF;    // [64][65]
    float* v2s = sm + V2_OFF;
    float* v3s = sm + V3_OFF;
    float* w1s = sm + W1_OFF;
    float* w2s = sm + W2_OFF;
    int*   i1s = (int*)(sm + I1_OFF);
    int*   i2s = (int*)(sm + I2_OFF);
    float* impP  = sm + IMPP_OFF;        // [4][64]
    float* loadP = sm + LOADP_OFF;       // [4][64]

    // write accumulators into logits tile
#pragma unroll
    for (int i = 0; i < 4; ++i)
#pragma unroll
        for (int j = 0; j < 8; ++j)
            logits_s[(ty * 4 + i) * LOGITS_STR + (tx * 8 + j)] = acc[i][j];

    // stage noise tile coalesced
    for (int i = tid; i < TOK_BLK * NEXP; i += NTHREADS) {
        int t = i >> 6, e = i & 63;
        noise_s[t * NOISE_STR + e] = noise[(size_t)(tok0 + t) * NEXP + e];
    }
    __syncthreads();

    // Phase E1: one thread per token — softplus, noisy logits, top-3, weights, outputs
    if (tid < TOK_BLK) {
        const int t = tid;
        float v1 = -CUDART_INF_F, v2 = -CUDART_INF_F, v3 = -CUDART_INF_F;
        int i1 = 0, i2 = 0;
#pragma unroll 4
        for (int e = 0; e < NEXP; ++e) {
            float lg = logits_s[t * LOGITS_STR + e];
            float nl = logits_s[t * LOGITS_STR + NEXP + e];
            // softplus = logaddexp(nl, 0), stable
            float sp = fmaxf(nl, 0.f) + log1pf(expf(-fabsf(nl)));
            float sd = sp + EPS;
            logits_s[t * LOGITS_STR + NEXP + e] = sd;  // overwrite with noise_std
            float nz = fmaf(noise_s[t * NOISE_STR + e], sd, lg);
            if (nz > v1)      { v3 = v2; v2 = v1; i2 = i1; v1 = nz; i1 = e; }
            else if (nz > v2) { v3 = v2; v2 = nz; i2 = e; }
            else if (nz > v3) { v3 = nz; }
        }
        // softmax over the two surviving logits
        float ed = expf(v2 - v1);               // <= 1
        float inv = 1.f / (1.f + ed);
        float w1 = inv, w2 = ed * inv;          // w1 >= w2

        const int tg = tok0 + t;
        out[2 * tg]                     = (float)i1;
        out[2 * tg + 1]                 = (float)i2;
        out[2 * N_TOKENS + 2 * tg]      = w1;
        out[2 * N_TOKENS + 2 * tg + 1]  = w2;
        out[4 * N_TOKENS + tg]          = w1;   // priority = max weight

        v2s[t] = v2; v3s[t] = v3; w1s[t] = w1; w2s[t] = w2; i1s[t] = i1; i2s[t] = i2;
    }
    __syncthreads();

    // Phase E2: thread (e, g) — importance & load partials, deterministic order
    {
        const int e = tid & 63;
        const int g = tid >> 6;     // 4 groups of 16 tokens
        float imp = 0.f, ld = 0.f;
#pragma unroll 4
        for (int t = g * 16; t < g * 16 + 16; ++t) {
            int ii1 = i1s[t], ii2 = i2s[t];
            bool in1 = (ii1 == e), in2 = (ii2 == e);
            if (in1) imp += w1s[t];
            if (in2) imp += w2s[t];
            float kth = (in1 || in2) ? v3s[t] : v2s[t];
            float sd  = logits_s[t * LOGITS_STR + NEXP + e];
            float lg  = logits_s[t * LOGITS_STR + e];
            float z   = (lg - kth) / (sd + EPS);
            ld += 0.5f * (1.f + erff(z * 0.70710678118654752f));
        }
        impP [g * 64 + e] = imp;
        loadP[g * 64 + e] = ld;
    }
    __syncthreads();

    if (tid < NEXP) {
        float si = 0.f, sl = 0.f;
#pragma unroll
        for (int g = 0; g < 4; ++g) { si += impP[g * 64 + tid]; sl += loadP[g * 64 + tid]; }
        g_imp_part [blockIdx.x * NEXP + tid] = si;
        g_load_part[blockIdx.x * NEXP + tid] = sl;
    }
}

__global__ void router_finalize_kernel(float* __restrict__ out)
{
    __shared__ float imp[NEXP], load[NEXP];
    const int tid = threadIdx.x;
    if (tid < NEXP) {
        float si = 0.f, sl = 0.f;
#pragma unroll 8
        for (int b = 0; b < NBLOCKS; ++b) {
            si += g_imp_part [b * NEXP + tid];
            sl += g_load_part[b * NEXP + tid];
        }
        imp[tid] = si; load[tid] = sl;
    }
    __syncthreads();
    if (tid == 0) {
        float mi = 0.f, ml = 0.f;
        for (int e = 0; e < NEXP; ++e) { mi += imp[e]; ml += load[e]; }
        mi *= (1.f / NEXP); ml *= (1.f / NEXP);
        float vi = 0.f, vl = 0.f;
        for (int e = 0; e < NEXP; ++e) {
            float di = imp[e] - mi, dl = load[e] - ml;
            vi += di * di; vl += dl * dl;
        }
        vi *= (1.f / NEXP); vl *= (1.f / NEXP);
        float cv_i = vi / (mi * mi + EPS);
        float cv_l = vl / (ml * ml + EPS);
        out[5 * N_TOKENS] = 0.1f * cv_i + 0.1f * cv_l;
    }
}

extern "C" void kernel_launch(void* const* d_in, const int* in_sizes, int n_in,
                              void* d_out, int out_size)
{
    const float* x     = (const float*)d_in[0];
    const float* noise = (const float*)d_in[1];
    const float* Wg    = (const float*)d_in[2];
    const float* Wn    = (const float*)d_in[3];
    float* out = (float*)d_out;

    cudaFuncSetAttribute(router_main_kernel,
                         cudaFuncAttributeMaxDynamicSharedMemorySize, SMEM_BYTES);
    router_main_kernel<<<NBLOCKS, NTHREADS, SMEM_BYTES>>>(x, noise, Wg, Wn, out);
    router_finalize_kernel<<<1, 64>>>(out);
}

// round 6
// speedup vs baseline: 1.4251x; 1.4251x over previous
#include <cuda_runtime.h>
#include <cuda_bf16.h>
#include <math_constants.h>
#include <cstdint>

#define N_TOKENS   16384
#define DIM        2048
#define NEXP       64
#define NCOLS      128
#define TOK_BLK    128
#define NBLOCKS    (N_TOKENS / TOK_BLK)   // 128
#define NTHREADS   256
#define KC         64
#define NCHUNK     (DIM / KC)             // 32
#define EPS        1e-9f
#define FIX_THR    2e-4f

#define PADB       144
#define TILE_BYTES (128 * PADB)           // 18432
#define A_HI       0
#define A_LO       TILE_BYTES
#define B_HI       (2 * TILE_BYTES)
#define B_LO       (3 * TILE_BYTES)
#define ST_SIZE    (4 * TILE_BYTES)       // 73728
#define SMEM_BYTES (1024 + 2 * ST_SIZE)

#define B_CHUNK_U16X (2 * TILE_BYTES / 16)   // 2304

// ---- static device scratch ----
__device__ uint4 g_wpack[NCHUNK * B_CHUNK_U16X];
__device__ float g_imp_part [NBLOCKS * NEXP];
__device__ float g_load_part[NBLOCKS * NEXP];
__device__ unsigned char g_flag[N_TOKENS];

// ======================= helpers =======================
__device__ __forceinline__ uint32_t smem_u32(const void* p) {
    uint32_t a;
    asm("{ .reg .u64 t; cvta.to.shared.u64 t, %1; cvt.u32.u64 %0, t; }" : "=r"(a) : "l"(p));
    return a;
}
__device__ __forceinline__ void ldsm_x4(uint32_t (&r)[4], uint32_t addr) {
    asm volatile("ldmatrix.sync.aligned.m8n8.x4.shared.b16 {%0,%1,%2,%3}, [%4];"
                 : "=r"(r[0]), "=r"(r[1]), "=r"(r[2]), "=r"(r[3]) : "r"(addr));
}
__device__ __forceinline__ void mma16816(float* d, const uint32_t* a, uint32_t b0, uint32_t b1) {
    asm volatile("mma.sync.aligned.m16n8k16.row.col.f32.bf16.bf16.f32 "
                 "{%0,%1,%2,%3}, {%4,%5,%6,%7}, {%8,%9}, {%0,%1,%2,%3};"
                 : "+f"(d[0]), "+f"(d[1]), "+f"(d[2]), "+f"(d[3])
                 : "r"(a[0]), "r"(a[1]), "r"(a[2]), "r"(a[3]), "r"(b0), "r"(b1));
}
#define CP_ASYNC16(dst, src) \
    asm volatile("cp.async.cg.shared.global [%0], [%1], 16;" :: "r"(dst), "l"(src))
#define CP_COMMIT()  asm volatile("cp.async.commit_group;")
#define CP_WAIT0()   asm volatile("cp.async.wait_group 0;")

__device__ __forceinline__ void split8(float4 a, float4 b, uint4& hi, uint4& lo) {
    float v[8] = {a.x, a.y, a.z, a.w, b.x, b.y, b.z, b.w};
    uint32_t h[4], l[4];
#pragma unroll
    for (int i = 0; i < 4; ++i) {
        __nv_bfloat16 h0 = __float2bfloat16(v[2*i]);
        __nv_bfloat16 h1 = __float2bfloat16(v[2*i+1]);
        float r0 = v[2*i]   - __bfloat162float(h0);
        float r1 = v[2*i+1] - __bfloat162float(h1);
        __nv_bfloat16 l0 = __float2bfloat16(r0);
        __nv_bfloat16 l1 = __float2bfloat16(r1);
        h[i] = (uint32_t)__bfloat16_as_ushort(h0) | ((uint32_t)__bfloat16_as_ushort(h1) << 16);
        l[i] = (uint32_t)__bfloat16_as_ushort(l0) | ((uint32_t)__bfloat16_as_ushort(l1) << 16);
    }
    hi = make_uint4(h[0], h[1], h[2], h[3]);
    lo = make_uint4(l[0], l[1], l[2], l[3]);
}

// ======================= W precompute =======================
__global__ void __launch_bounds__(256) wpack_kernel(const float* __restrict__ Wg,
                                                    const float* __restrict__ Wn) {
    int id = blockIdx.x * 256 + threadIdx.x;
    int chunk = id >> 10;
    int rem   = id & 1023;
    int col = rem >> 3, u = rem & 7;
    const float* src = (col < NEXP ? Wg + (size_t)col * DIM : Wn + (size_t)(col - NEXP) * DIM)
                       + chunk * KC + u * 8;
    float4 a = ((const float4*)src)[0];
    float4 b = ((const float4*)src)[1];
    uint4 hi, lo;
    split8(a, b, hi, lo);
    char* base = (char*)g_wpack + (size_t)chunk * (2 * TILE_BYTES);
    *(uint4*)(base + col * PADB + u * 16)              = hi;
    *(uint4*)(base + TILE_BYTES + col * PADB + u * 16) = lo;
}

// ======================= main fused kernel =======================
__global__ void __launch_bounds__(NTHREADS)
router_main_kernel(const float* __restrict__ x,
                   const float* __restrict__ noise,
                   float* __restrict__ out)
{
    extern __shared__ char sm[];
    const uint32_t smb = smem_u32(sm);
    const uint32_t stb = (smb + 1023u) & ~1023u;
    char* st_ptr = sm + (stb - smb);

    const int tid  = threadIdx.x;
    const int wid  = tid >> 5;
    const int lane = tid & 31;
    const int wm   = wid >> 1;
    const int wn   = wid & 1;
    const int tok0 = blockIdx.x * TOK_BLK;

    const int arow = tid >> 3, au = tid & 7;

    float acc[2][8][4];
#pragma unroll
    for (int i = 0; i < 2; ++i)
#pragma unroll
        for (int j = 0; j < 8; ++j)
#pragma unroll
            for (int q = 0; q < 4; ++q) acc[i][j][q] = 0.f;

    // ---- prologue ----
    {
        const uint4* src = g_wpack;
        uint32_t d = stb + B_HI;
#pragma unroll
        for (int t = 0; t < 9; ++t) {
            int idx = tid + t * 256;
            CP_ASYNC16(d + idx * 16, src + idx);
        }
        CP_COMMIT();

        float4 ar[8];
#pragma unroll
        for (int t = 0; t < 4; ++t) {
            const float4* p = (const float4*)(x + (size_t)(tok0 + arow + t * 32) * DIM + au * 8);
            ar[2*t]   = p[0];
            ar[2*t+1] = p[1];
        }
#pragma unroll
        for (int t = 0; t < 4; ++t) {
            uint4 hi, lo;
            split8(ar[2*t], ar[2*t+1], hi, lo);
            int r = arow + t * 32;
            *(uint4*)(st_ptr + A_HI + r * PADB + au * 16) = hi;
            *(uint4*)(st_ptr + A_LO + r * PADB + au * 16) = lo;
        }
        CP_WAIT0();
        __syncthreads();
    }

    const uint32_t a_lane = (uint32_t)((wm * 32 + (lane & 15)) * PADB + (lane >> 4) * 16);
    const uint32_t b_lane = (uint32_t)((wn * 64 + (lane & 15)) * PADB + (lane >> 4) * 16);

    for (int c = 0; c < NCHUNK; ++c) {
        const int buf = c & 1;
        const uint32_t sb = stb + buf * ST_SIZE;
        const bool pf = (c + 1 < NCHUNK);
        char* stn = st_ptr + (buf ^ 1) * ST_SIZE;

        float4 ar[8];
        if (pf) {
            const uint4* src = g_wpack + (size_t)(c + 1) * B_CHUNK_U16X;
            uint32_t d = stb + (buf ^ 1) * ST_SIZE + B_HI;
#pragma unroll
            for (int t = 0; t < 9; ++t) {
                int idx = tid + t * 256;
                CP_ASYNC16(d + idx * 16, src + idx);
            }
            CP_COMMIT();
            const int koff = (c + 1) * KC;
#pragma unroll
            for (int t = 0; t < 4; ++t) {
                const float4* p = (const float4*)(x + (size_t)(tok0 + arow + t * 32) * DIM + koff + au * 8);
                ar[2*t]   = p[0];
                ar[2*t+1] = p[1];
            }
        }

        // ---- MMA: 3-pass bf16x2 ----
#pragma unroll
        for (int ks = 0; ks < 4; ++ks) {
            const uint32_t ko = ks * 32;
            uint32_t ah[2][4], al[2][4];
            ldsm_x4(ah[0], sb + A_HI + a_lane + ko);
            ldsm_x4(ah[1], sb + A_HI + a_lane + 16 * PADB + ko);
            ldsm_x4(al[0], sb + A_LO + a_lane + ko);
            ldsm_x4(al[1], sb + A_LO + a_lane + 16 * PADB + ko);
            uint32_t bh[4][4], bl[4][4];
#pragma unroll
            for (int p = 0; p < 4; ++p) {
                ldsm_x4(bh[p], sb + B_HI + b_lane + p * 16 * PADB + ko);
                ldsm_x4(bl[p], sb + B_LO + b_lane + p * 16 * PADB + ko);
            }
#pragma unroll
            for (int mt = 0; mt < 2; ++mt)
#pragma unroll
                for (int p = 0; p < 4; ++p)
#pragma unroll
                    for (int h = 0; h < 2; ++h) {
                        float* d = acc[mt][2 * p + h];
                        mma16816(d, ah[mt], bh[p][h], bh[p][2 + h]);
                        mma16816(d, ah[mt], bl[p][h], bl[p][2 + h]);
                        mma16816(d, al[mt], bh[p][h], bh[p][2 + h]);
                    }
        }

        if (pf) {
#pragma unroll
            for (int t = 0; t < 4; ++t) {
                uint4 hi, lo;
                split8(ar[2*t], ar[2*t+1], hi, lo);
                int r = arow + t * 32;
                *(uint4*)(stn + A_HI + r * PADB + au * 16) = hi;
                *(uint4*)(stn + A_LO + r * PADB + au * 16) = lo;
            }
            CP_WAIT0();
        }
        __syncthreads();
    }

    // ---------------- epilogue ----------------
    float* smf = (float*)st_ptr;
    const int LSTR = 129;
    const int LOGI = 0;
    const int NOI  = 128 * 129, NSTR = 65;
    const int V2O  = NOI + 128 * 65;
    const int V3O  = V2O + 128, W1O = V3O + 128, W2O = W1O + 128;
    const int I1O  = W2O + 128, I2O = I1O + 128;
    const int IMPO = I2O + 128, LDO = IMPO + 256;
    const int FLGO = LDO + 256;                      // [128] int flags

#pragma unroll
    for (int mt = 0; mt < 2; ++mt)
#pragma unroll
        for (int nt = 0; nt < 8; ++nt)
#pragma unroll
            for (int ci = 0; ci < 4; ++ci) {
                int row = wm * 32 + mt * 16 + (lane >> 2) + (ci >> 1) * 8;
                int col = wn * 64 + nt * 8 + (lane & 3) * 2 + (ci & 1);
                smf[LOGI + row * LSTR + col] = acc[mt][nt][ci];
            }

    for (int i = tid; i < TOK_BLK * NEXP; i += NTHREADS) {
        int t = i >> 6, e = i & 63;
        smf[NOI + t * NSTR + e] = noise[(size_t)(tok0 + t) * NEXP + e];
    }
    __syncthreads();

    // E1: one thread per token (+ ambiguity flag)
    if (tid < TOK_BLK) {
        const int t = tid;
        float v1 = -CUDART_INF_F, v2 = -CUDART_INF_F, v3 = -CUDART_INF_F;
        int i1 = 0, i2 = 0;
#pragma unroll 4
        for (int e = 0; e < NEXP; ++e) {
            float lg = smf[LOGI + t * LSTR + e];
            float nl = smf[LOGI + t * LSTR + NEXP + e];
            float sp = fmaxf(nl, 0.f) + log1pf(expf(-fabsf(nl)));
            float sd = sp + EPS;
            smf[LOGI + t * LSTR + NEXP + e] = sd;
            float nz = fmaf(smf[NOI + t * NSTR + e], sd, lg);
            if (nz > v1)      { v3 = v2; v2 = v1; i2 = i1; v1 = nz; i1 = e; }
            else if (nz > v2) { v3 = v2; v2 = nz; i2 = e; }
            else if (nz > v3) { v3 = nz; }
        }
        float ed  = expf(v2 - v1);
        float inv = 1.f / (1.f + ed);
        float w1 = inv, w2 = ed * inv;

        const int tg = tok0 + t;
        int flag = ((v1 - v2) < FIX_THR) || ((v2 - v3) < FIX_THR);
        out[2 * tg]                    = (float)i1;
        out[2 * tg + 1]                = (float)i2;
        out[2 * N_TOKENS + 2 * tg]     = w1;
        out[2 * N_TOKENS + 2 * tg + 1] = w2;
        out[4 * N_TOKENS + tg]         = w1;
        g_flag[tg] = (unsigned char)flag;
        ((int*)(smf + FLGO))[t] = flag;
        smf[V2O + t] = v2; smf[V3O + t] = v3;
        smf[W1O + t] = w1; smf[W2O + t] = w2;
        ((int*)(smf + I1O))[t] = i1; ((int*)(smf + I2O))[t] = i2;
    }
    __syncthreads();

    // E2: partials, skipping flagged tokens (fixup adds them exactly)
    {
        const int e = tid & 63, g = tid >> 6;
        float imp = 0.f, ld = 0.f;
#pragma unroll 4
        for (int t = g * 32; t < g * 32 + 32; ++t) {
            if (((int*)(smf + FLGO))[t]) continue;
            int ii1 = ((int*)(smf + I1O))[t], ii2 = ((int*)(smf + I2O))[t];
            bool in1 = (ii1 == e), in2 = (ii2 == e);
            if (in1) imp += smf[W1O + t];
            if (in2) imp += smf[W2O + t];
            float kth = (in1 || in2) ? smf[V3O + t] : smf[V2O + t];
            float sd  = smf[LOGI + t * LSTR + NEXP + e];
            float lg  = smf[LOGI + t * LSTR + e];
            float z   = (lg - kth) / (sd + EPS);
            ld += 0.5f * (1.f + erff(z * 0.70710678118654752f));
        }
        smf[IMPO + g * 64 + e] = imp;
        smf[LDO  + g * 64 + e] = ld;
    }
    __syncthreads();

    if (tid < NEXP) {
        float si = 0.f, sl = 0.f;
#pragma unroll
        for (int g = 0; g < 4; ++g) { si += smf[IMPO + g * 64 + tid]; sl += smf[LDO + g * 64 + tid]; }
        g_imp_part [blockIdx.x * NEXP + tid] = si;
        g_load_part[blockIdx.x * NEXP + tid] = sl;
    }
}

// ======================= fixup: exact recompute of flagged tokens =======================
__global__ void __launch_bounds__(256)
router_fixup_kernel(const float* __restrict__ x, const float* __restrict__ noise,
                    const float* __restrict__ Wg, const float* __restrict__ Wn,
                    float* __restrict__ out)
{
    __shared__ float xs[DIM];
    __shared__ float lgf[NCOLS];
    __shared__ float sds[NEXP], nzs[NEXP];
    __shared__ float pair_s[256], pair_c[256];
    __shared__ float sv2, sv3, sw1, sw2;
    __shared__ int   si1, si2;
    const int tid = threadIdx.x;
    const int base = blockIdx.x * 128;

    float imp_acc = 0.f, ld_acc = 0.f;     // per-thread (expert=tid<64) accumulators

    for (int t = base; t < base + 128; ++t) {
        if (!g_flag[t]) continue;

        for (int i = tid; i < DIM / 4; i += 256)
            ((float4*)xs)[i] = ((const float4*)(x + (size_t)t * DIM))[i];
        __syncthreads();

        // compensated dot: col = tid>>1, half = tid&1
        const int col = tid >> 1, half = tid & 1;
        const float* w = (col < NEXP ? Wg + (size_t)col * DIM : Wn + (size_t)(col - NEXP) * DIM);
        float s = 0.f, c = 0.f;
        for (int k = half * 1024; k < half * 1024 + 1024; ++k) {
            float xv = xs[k], wv = w[k];
            float p  = xv * wv;
            float e  = fmaf(xv, wv, -p);
            float t0 = s + p;
            c += (fabsf(s) >= fabsf(p)) ? ((s - t0) + p) : ((p - t0) + s);
            s = t0;
            c += e;
        }
        pair_s[tid] = s; pair_c[tid] = c;
        __syncthreads();

        if (tid < NCOLS) {
            double v = (double)pair_s[2*tid] + (double)pair_c[2*tid]
                     + (double)pair_s[2*tid+1] + (double)pair_c[2*tid+1];
            lgf[tid] = (float)v;
        }
        __syncthreads();

        if (tid < NEXP) {
            float nl = lgf[NEXP + tid];
            float sp = fmaxf(nl, 0.f) + log1pf(expf(-fabsf(nl)));
            sds[tid] = sp + EPS;
            nzs[tid] = fmaf(noise[(size_t)t * NEXP + tid], sds[tid], lgf[tid]);
        }
        __syncthreads();

        if (tid == 0) {
            float v1 = -CUDART_INF_F, v2 = -CUDART_INF_F, v3 = -CUDART_INF_F;
            int i1 = 0, i2 = 0;
            for (int e = 0; e < NEXP; ++e) {
                float nz = nzs[e];
                if (nz > v1)      { v3 = v2; v2 = v1; i2 = i1; v1 = nz; i1 = e; }
                else if (nz > v2) { v3 = v2; v2 = nz; i2 = e; }
                else if (nz > v3) { v3 = nz; }
            }
            float ed  = expf(v2 - v1);
            float inv = 1.f / (1.f + ed);
            float w1 = inv, w2 = ed * inv;
            out[2 * t]                    = (float)i1;
            out[2 * t + 1]                = (float)i2;
            out[2 * N_TOKENS + 2 * t]     = w1;
            out[2 * N_TOKENS + 2 * t + 1] = w2;
            out[4 * N_TOKENS + t]         = w1;
            sv2 = v2; sv3 = v3; sw1 = w1; sw2 = w2; si1 = i1; si2 = i2;
        }
        __syncthreads();

        if (tid < NEXP) {
            bool in1 = (si1 == tid), in2 = (si2 == tid);
            if (in1) imp_acc += sw1;
            if (in2) imp_acc += sw2;
            float kth = (in1 || in2) ? sv3 : sv2;
            float z = (lgf[tid] - kth) / (sds[tid] + EPS);
            ld_acc += 0.5f * (1.f + erff(z * 0.70710678118654752f));
        }
        __syncthreads();
    }

    if (tid < NEXP) {
        g_imp_part [blockIdx.x * NEXP + tid] += imp_acc;
        g_load_part[blockIdx.x * NEXP + tid] += ld_acc;
    }
}

// ======================= finalize =======================
__global__ void __launch_bounds__(512) router_finalize_kernel(float* __restrict__ out)
{
    __shared__ float pimp[8][64], pld[8][64];
    const int tid = threadIdx.x;
    const int e = tid & 63, g = tid >> 6;
    float si = 0.f, sl = 0.f;
#pragma unroll
    for (int b = g; b < NBLOCKS; b += 8) {
        si += g_imp_part [b * NEXP + e];
        sl += g_load_part[b * NEXP + e];
    }
    pimp[g][e] = si; pld[g][e] = sl;
    __syncthreads();
    if (tid < 64) {
        float a = 0.f, b = 0.f;
#pragma unroll
        for (int q = 0; q < 8; ++q) { a += pimp[q][tid]; b += pld[q][tid]; }
        pimp[0][tid] = a; pld[0][tid] = b;
    }
    __syncthreads();
    if (tid == 0) {
        float mi = 0.f, ml = 0.f;
        for (int q = 0; q < NEXP; ++q) { mi += pimp[0][q]; ml += pld[0][q]; }
        mi *= (1.f / NEXP); ml *= (1.f / NEXP);
        float vi = 0.f, vl = 0.f;
        for (int q = 0; q < NEXP; ++q) {
            float di = pimp[0][q] - mi, dl = pld[0][q] - ml;
            vi += di * di; vl += dl * dl;
        }
        vi *= (1.f / NEXP); vl *= (1.f / NEXP);
        out[5 * N_TOKENS] = 0.1f * (vi / (mi * mi + EPS)) + 0.1f * (vl / (ml * ml + EPS));
    }
}

extern "C" void kernel_launch(void* const* d_in, const int* in_sizes, int n_in,
                              void* d_out, int out_size)
{
    const float* x     = (const float*)d_in[0];
    const float* noise = (const float*)d_in[1];
    const float* Wg    = (const float*)d_in[2];
    const float* Wn    = (const float*)d_in[3];
    float* out = (float*)d_out;

    cudaFuncSetAttribute(router_main_kernel,
                         cudaFuncAttributeMaxDynamicSharedMemorySize, SMEM_BYTES);
    wpack_kernel<<<128, 256>>>(Wg, Wn);
    router_main_kernel<<<NBLOCKS, NTHREADS, SMEM_BYTES>>>(x, noise, out);
    router_fixup_kernel<<<128, 256>>>(x, noise, Wg, Wn, out);
    router_finalize_kernel<<<1, 512>>>(out);
}

// round 7
// speedup vs baseline: 1.4258x; 1.0005x over previous
#include <cuda_runtime.h>
#include <cuda_bf16.h>
#include <math_constants.h>
#include <cstdint>

#define N_TOKENS   16384
#define DIM        2048
#define NEXP       64
#define NCOLS      128
#define TOK_BLK    128
#define NBLOCKS    (N_TOKENS / TOK_BLK)   // 128
#define NTHREADS   512
#define KC         64
#define NCHUNK     (DIM / KC)             // 32
#define EPS        1e-9f
#define FIX_THR    2e-4f

#define PADB       144
#define TILE_BYTES (128 * PADB)           // 18432
#define A_HI       0
#define A_LO       TILE_BYTES
#define B_HI       (2 * TILE_BYTES)
#define B_LO       (3 * TILE_BYTES)
#define ST_SIZE    (4 * TILE_BYTES)       // 73728
#define SMEM_BYTES (1024 + 2 * ST_SIZE)

#define B_CHUNK_U16X (2 * TILE_BYTES / 16)   // 2304

// ---- static device scratch ----
__device__ uint4 g_wpack[NCHUNK * B_CHUNK_U16X];
__device__ float g_imp_part [NBLOCKS * NEXP];
__device__ float g_load_part[NBLOCKS * NEXP];
__device__ unsigned char g_flag[N_TOKENS];

// ======================= helpers =======================
__device__ __forceinline__ uint32_t smem_u32(const void* p) {
    uint32_t a;
    asm("{ .reg .u64 t; cvta.to.shared.u64 t, %1; cvt.u32.u64 %0, t; }" : "=r"(a) : "l"(p));
    return a;
}
__device__ __forceinline__ void ldsm_x4(uint32_t (&r)[4], uint32_t addr) {
    asm volatile("ldmatrix.sync.aligned.m8n8.x4.shared.b16 {%0,%1,%2,%3}, [%4];"
                 : "=r"(r[0]), "=r"(r[1]), "=r"(r[2]), "=r"(r[3]) : "r"(addr));
}
__device__ __forceinline__ void mma16816(float* d, const uint32_t* a, uint32_t b0, uint32_t b1) {
    asm volatile("mma.sync.aligned.m16n8k16.row.col.f32.bf16.bf16.f32 "
                 "{%0,%1,%2,%3}, {%4,%5,%6,%7}, {%8,%9}, {%0,%1,%2,%3};"
                 : "+f"(d[0]), "+f"(d[1]), "+f"(d[2]), "+f"(d[3])
                 : "r"(a[0]), "r"(a[1]), "r"(a[2]), "r"(a[3]), "r"(b0), "r"(b1));
}
#define CP_ASYNC16(dst, src) \
    asm volatile("cp.async.cg.shared.global [%0], [%1], 16;" :: "r"(dst), "l"(src))
#define CP_COMMIT()  asm volatile("cp.async.commit_group;")
#define CP_WAIT0()   asm volatile("cp.async.wait_group 0;")

__device__ __forceinline__ void split8(float4 a, float4 b, uint4& hi, uint4& lo) {
    float v[8] = {a.x, a.y, a.z, a.w, b.x, b.y, b.z, b.w};
    uint32_t h[4], l[4];
#pragma unroll
    for (int i = 0; i < 4; ++i) {
        __nv_bfloat16 h0 = __float2bfloat16(v[2*i]);
        __nv_bfloat16 h1 = __float2bfloat16(v[2*i+1]);
        float r0 = v[2*i]   - __bfloat162float(h0);
        float r1 = v[2*i+1] - __bfloat162float(h1);
        __nv_bfloat16 l0 = __float2bfloat16(r0);
        __nv_bfloat16 l1 = __float2bfloat16(r1);
        h[i] = (uint32_t)__bfloat16_as_ushort(h0) | ((uint32_t)__bfloat16_as_ushort(h1) << 16);
        l[i] = (uint32_t)__bfloat16_as_ushort(l0) | ((uint32_t)__bfloat16_as_ushort(l1) << 16);
    }
    hi = make_uint4(h[0], h[1], h[2], h[3]);
    lo = make_uint4(l[0], l[1], l[2], l[3]);
}

// ======================= W precompute =======================
__global__ void __launch_bounds__(256) wpack_kernel(const float* __restrict__ Wg,
                                                    const float* __restrict__ Wn) {
    int id = blockIdx.x * 256 + threadIdx.x;
    int chunk = id >> 10;
    int rem   = id & 1023;
    int col = rem >> 3, u = rem & 7;
    const float* src = (col < NEXP ? Wg + (size_t)col * DIM : Wn + (size_t)(col - NEXP) * DIM)
                       + chunk * KC + u * 8;
    float4 a = ((const float4*)src)[0];
    float4 b = ((const float4*)src)[1];
    uint4 hi, lo;
    split8(a, b, hi, lo);
    char* base = (char*)g_wpack + (size_t)chunk * (2 * TILE_BYTES);
    *(uint4*)(base + col * PADB + u * 16)              = hi;
    *(uint4*)(base + TILE_BYTES + col * PADB + u * 16) = lo;
}

// ======================= main fused kernel =======================
__global__ void __launch_bounds__(NTHREADS)
router_main_kernel(const float* __restrict__ x,
                   const float* __restrict__ noise,
                   float* __restrict__ out)
{
    extern __shared__ char sm[];
    const uint32_t smb = smem_u32(sm);
    const uint32_t stb = (smb + 1023u) & ~1023u;
    char* st_ptr = sm + (stb - smb);

    const int tid  = threadIdx.x;
    const int wid  = tid >> 5;           // 0..15
    const int lane = tid & 31;
    const int wm   = wid >> 1;           // 0..7  (16 rows each)
    const int wn   = wid & 1;            // 0..1  (64 cols each)
    const int tok0 = blockIdx.x * TOK_BLK;

    // A-stage: 1024 (row,u) assignments over 512 threads -> 2 each
    const int arow = tid >> 3, au = tid & 7;   // idx = tid + t*512

    float acc[8][4];
#pragma unroll
    for (int j = 0; j < 8; ++j)
#pragma unroll
        for (int q = 0; q < 4; ++q) acc[j][q] = 0.f;

    // ---- prologue: stage chunk 0 ----
    {
        const uint4* src = g_wpack;
        uint32_t d = stb + B_HI;
#pragma unroll
        for (int t = 0; t < 5; ++t) {
            int idx = tid + t * 512;
            if (idx < B_CHUNK_U16X) CP_ASYNC16(d + idx * 16, src + idx);
        }
        CP_COMMIT();

        float4 ar[4];
#pragma unroll
        for (int t = 0; t < 2; ++t) {
            const float4* p = (const float4*)(x + (size_t)(tok0 + arow + t * 64) * DIM + au * 8);
            ar[2*t]   = p[0];
            ar[2*t+1] = p[1];
        }
#pragma unroll
        for (int t = 0; t < 2; ++t) {
            uint4 hi, lo;
            split8(ar[2*t], ar[2*t+1], hi, lo);
            int r = arow + t * 64;
            *(uint4*)(st_ptr + A_HI + r * PADB + au * 16) = hi;
            *(uint4*)(st_ptr + A_LO + r * PADB + au * 16) = lo;
        }
        CP_WAIT0();
        __syncthreads();
    }

    const uint32_t a_lane = (uint32_t)((wm * 16 + (lane & 15)) * PADB + (lane >> 4) * 16);
    const uint32_t b_lane = (uint32_t)((wn * 64 + (lane & 15)) * PADB + (lane >> 4) * 16);

    for (int c = 0; c < NCHUNK; ++c) {
        const int buf = c & 1;
        const uint32_t sb = stb + buf * ST_SIZE;
        const bool pf = (c + 1 < NCHUNK);
        char* stn = st_ptr + (buf ^ 1) * ST_SIZE;

        float4 ar[4];
        if (pf) {
            const uint4* src = g_wpack + (size_t)(c + 1) * B_CHUNK_U16X;
            uint32_t d = stb + (buf ^ 1) * ST_SIZE + B_HI;
#pragma unroll
            for (int t = 0; t < 5; ++t) {
                int idx = tid + t * 512;
                if (idx < B_CHUNK_U16X) CP_ASYNC16(d + idx * 16, src + idx);
            }
            CP_COMMIT();
            const int koff = (c + 1) * KC;
#pragma unroll
            for (int t = 0; t < 2; ++t) {
                const float4* p = (const float4*)(x + (size_t)(tok0 + arow + t * 64) * DIM + koff + au * 8);
                ar[2*t]   = p[0];
                ar[2*t+1] = p[1];
            }
        }

        // ---- MMA over chunk c: pass-major (hh, then hl, then lh) ----
#pragma unroll
        for (int ks = 0; ks < 4; ++ks) {
            const uint32_t ko = ks * 32;
            uint32_t ah[4], al[4];
            ldsm_x4(ah, sb + A_HI + a_lane + ko);
            ldsm_x4(al, sb + A_LO + a_lane + ko);
            uint32_t bh[4][4], bl[4][4];
#pragma unroll
            for (int p = 0; p < 4; ++p) {
                ldsm_x4(bh[p], sb + B_HI + b_lane + p * 16 * PADB + ko);
                ldsm_x4(bl[p], sb + B_LO + b_lane + p * 16 * PADB + ko);
            }
            // pass 1: hh
#pragma unroll
            for (int p = 0; p < 4; ++p)
#pragma unroll
                for (int h = 0; h < 2; ++h)
                    mma16816(acc[2 * p + h], ah, bh[p][h], bh[p][2 + h]);
            // pass 2: h·lo(B)
#pragma unroll
            for (int p = 0; p < 4; ++p)
#pragma unroll
                for (int h = 0; h < 2; ++h)
                    mma16816(acc[2 * p + h], ah, bl[p][h], bl[p][2 + h]);
            // pass 3: lo(A)·h
#pragma unroll
            for (int p = 0; p < 4; ++p)
#pragma unroll
                for (int h = 0; h < 2; ++h)
                    mma16816(acc[2 * p + h], al, bh[p][h], bh[p][2 + h]);
        }

        if (pf) {
#pragma unroll
            for (int t = 0; t < 2; ++t) {
                uint4 hi, lo;
                split8(ar[2*t], ar[2*t+1], hi, lo);
                int r = arow + t * 64;
                *(uint4*)(stn + A_HI + r * PADB + au * 16) = hi;
                *(uint4*)(stn + A_LO + r * PADB + au * 16) = lo;
            }
            CP_WAIT0();
        }
        __syncthreads();
    }

    // ---------------- epilogue ----------------
    float* smf = (float*)st_ptr;
    const int LSTR = 129;
    const int LOGI = 0;
    const int NOI  = 128 * 129, NSTR = 65;
    const int V2O  = NOI + 128 * 65;
    const int V3O  = V2O + 128, W1O = V3O + 128, W2O = W1O + 128;
    const int I1O  = W2O + 128, I2O = I1O + 128;
    const int IMPO = I2O + 128, LDO = IMPO + 512;   // [8][64] each
    const int FLGO = LDO + 512;                     // [128] int flags

#pragma unroll
    for (int nt = 0; nt < 8; ++nt)
#pragma unroll
        for (int ci = 0; ci < 4; ++ci) {
            int row = wm * 16 + (lane >> 2) + (ci >> 1) * 8;
            int col = wn * 64 + nt * 8 + (lane & 3) * 2 + (ci & 1);
            smf[LOGI + row * LSTR + col] = acc[nt][ci];
        }

    for (int i = tid; i < TOK_BLK * NEXP; i += NTHREADS) {
        int t = i >> 6, e = i & 63;
        smf[NOI + t * NSTR + e] = noise[(size_t)(tok0 + t) * NEXP + e];
    }
    __syncthreads();

    // E1: one thread per token (+ ambiguity flag)
    if (tid < TOK_BLK) {
        const int t = tid;
        float v1 = -CUDART_INF_F, v2 = -CUDART_INF_F, v3 = -CUDART_INF_F;
        int i1 = 0, i2 = 0;
#pragma unroll 4
        for (int e = 0; e < NEXP; ++e) {
            float lg = smf[LOGI + t * LSTR + e];
            float nl = smf[LOGI + t * LSTR + NEXP + e];
            float sp = fmaxf(nl, 0.f) + log1pf(expf(-fabsf(nl)));
            float sd = sp + EPS;
            smf[LOGI + t * LSTR + NEXP + e] = sd;
            float nz = fmaf(smf[NOI + t * NSTR + e], sd, lg);
            if (nz > v1)      { v3 = v2; v2 = v1; i2 = i1; v1 = nz; i1 = e; }
            else if (nz > v2) { v3 = v2; v2 = nz; i2 = e; }
            else if (nz > v3) { v3 = nz; }
        }
        float ed  = expf(v2 - v1);
        float inv = 1.f / (1.f + ed);
        float w1 = inv, w2 = ed * inv;

        const int tg = tok0 + t;
        int flag = ((v1 - v2) < FIX_THR) || ((v2 - v3) < FIX_THR);
        out[2 * tg]                    = (float)i1;
        out[2 * tg + 1]                = (float)i2;
        out[2 * N_TOKENS + 2 * tg]     = w1;
        out[2 * N_TOKENS + 2 * tg + 1] = w2;
        out[4 * N_TOKENS + tg]         = w1;
        g_flag[tg] = (unsigned char)flag;
        ((int*)(smf + FLGO))[t] = flag;
        smf[V2O + t] = v2; smf[V3O + t] = v3;
        smf[W1O + t] = w1; smf[W2O + t] = w2;
        ((int*)(smf + I1O))[t] = i1; ((int*)(smf + I2O))[t] = i2;
    }
    __syncthreads();

    // E2: partials, skipping flagged tokens (fixup adds them exactly)
    {
        const int e = tid & 63, g = tid >> 6;   // 8 groups x 16 tokens
        float imp = 0.f, ld = 0.f;
#pragma unroll 4
        for (int t = g * 16; t < g * 16 + 16; ++t) {
            if (((int*)(smf + FLGO))[t]) continue;
            int ii1 = ((int*)(smf + I1O))[t], ii2 = ((int*)(smf + I2O))[t];
            bool in1 = (ii1 == e), in2 = (ii2 == e);
            if (in1) imp += smf[W1O + t];
            if (in2) imp += smf[W2O + t];
            float kth = (in1 || in2) ? smf[V3O + t] : smf[V2O + t];
            float sd  = smf[LOGI + t * LSTR + NEXP + e];
            float lg  = smf[LOGI + t * LSTR + e];
            float z   = (lg - kth) / (sd + EPS);
            ld += 0.5f * (1.f + erff(z * 0.70710678118654752f));
        }
        smf[IMPO + g * 64 + e] = imp;
        smf[LDO  + g * 64 + e] = ld;
    }
    __syncthreads();

    if (tid < NEXP) {
        float si = 0.f, sl = 0.f;
#pragma unroll
        for (int g = 0; g < 8; ++g) { si += smf[IMPO + g * 64 + tid]; sl += smf[LDO + g * 64 + tid]; }
        g_imp_part [blockIdx.x * NEXP + tid] = si;
        g_load_part[blockIdx.x * NEXP + tid] = sl;
    }
}

// ======================= fixup: exact recompute of flagged tokens =======================
__global__ void __launch_bounds__(256)
router_fixup_kernel(const float* __restrict__ x, const float* __restrict__ noise,
                    const float* __restrict__ Wg, const float* __restrict__ Wn,
                    float* __restrict__ out)
{
    __shared__ float xs[DIM];
    __shared__ float lgf[NCOLS];
    __shared__ float sds[NEXP], nzs[NEXP];
    __shared__ float pair_s[256], pair_c[256];
    __shared__ float sv2, sv3, sw1, sw2;
    __shared__ int   si1, si2;
    const int tid = threadIdx.x;
    const int base = blockIdx.x * 128;

    float imp_acc = 0.f, ld_acc = 0.f;

    for (int t = base; t < base + 128; ++t) {
        if (!g_flag[t]) continue;

        for (int i = tid; i < DIM / 4; i += 256)
            ((float4*)xs)[i] = ((const float4*)(x + (size_t)t * DIM))[i];
        __syncthreads();

        const int col = tid >> 1, half = tid & 1;
        const float* w = (col < NEXP ? Wg + (size_t)col * DIM : Wn + (size_t)(col - NEXP) * DIM);
        float s = 0.f, c = 0.f;
        for (int k = half * 1024; k < half * 1024 + 1024; ++k) {
            float xv = xs[k], wv = w[k];
            float p  = xv * wv;
            float e  = fmaf(xv, wv, -p);
            float t0 = s + p;
            c += (fabsf(s) >= fabsf(p)) ? ((s - t0) + p) : ((p - t0) + s);
            s = t0;
            c += e;
        }
        pair_s[tid] = s; pair_c[tid] = c;
        __syncthreads();

        if (tid < NCOLS) {
            double v = (double)pair_s[2*tid] + (double)pair_c[2*tid]
                     + (double)pair_s[2*tid+1] + (double)pair_c[2*tid+1];
            lgf[tid] = (float)v;
        }
        __syncthreads();

        if (tid < NEXP) {
            float nl = lgf[NEXP + tid];
            float sp = fmaxf(nl, 0.f) + log1pf(expf(-fabsf(nl)));
            sds[tid] = sp + EPS;
            nzs[tid] = fmaf(noise[(size_t)t * NEXP + tid], sds[tid], lgf[tid]);
        }
        __syncthreads();

        if (tid == 0) {
            float v1 = -CUDART_INF_F, v2 = -CUDART_INF_F, v3 = -CUDART_INF_F;
            int i1 = 0, i2 = 0;
            for (int e = 0; e < NEXP; ++e) {
                float nz = nzs[e];
                if (nz > v1)      { v3 = v2; v2 = v1; i2 = i1; v1 = nz; i1 = e; }
                else if (nz > v2) { v3 = v2; v2 = nz; i2 = e; }
                else if (nz > v3) { v3 = nz; }
            }
            float ed  = expf(v2 - v1);
            float inv = 1.f / (1.f + ed);
            float w1 = inv, w2 = ed * inv;
            out[2 * t]                    = (float)i1;
            out[2 * t + 1]                = (float)i2;
            out[2 * N_TOKENS + 2 * t]     = w1;
            out[2 * N_TOKENS + 2 * t + 1] = w2;
            out[4 * N_TOKENS + t]         = w1;
            sv2 = v2; sv3 = v3; sw1 = w1; sw2 = w2; si1 = i1; si2 = i2;
        }
        __syncthreads();

        if (tid < NEXP) {
            bool in1 = (si1 == tid), in2 = (si2 == tid);
            if (in1) imp_acc += sw1;
            if (in2) imp_acc += sw2;
            float kth = (in1 || in2) ? sv3 : sv2;
            float z = (lgf[tid] - kth) / (sds[tid] + EPS);
            ld_acc += 0.5f * (1.f + erff(z * 0.70710678118654752f));
        }
        __syncthreads();
    }

    if (tid < NEXP) {
        g_imp_part [blockIdx.x * NEXP + tid] += imp_acc;
        g_load_part[blockIdx.x * NEXP + tid] += ld_acc;
    }
}

// ======================= finalize =======================
__global__ void __launch_bounds__(512) router_finalize_kernel(float* __restrict__ out)
{
    __shared__ float pimp[8][64], pld[8][64];
    const int tid = threadIdx.x;
    const int e = tid & 63, g = tid >> 6;
    float si = 0.f, sl = 0.f;
#pragma unroll
    for (int b = g; b < NBLOCKS; b += 8) {
        si += g_imp_part [b * NEXP + e];
        sl += g_load_part[b * NEXP + e];
    }
    pimp[g][e] = si; pld[g][e] = sl;
    __syncthreads();
    if (tid < 64) {
        float a = 0.f, b = 0.f;
#pragma unroll
        for (int q = 0; q < 8; ++q) { a += pimp[q][tid]; b += pld[q][tid]; }
        pimp[0][tid] = a; pld[0][tid] = b;
    }
    __syncthreads();
    if (tid == 0) {
        float mi = 0.f, ml = 0.f;
        for (int q = 0; q < NEXP; ++q) { mi += pimp[0][q]; ml += pld[0][q]; }
        mi *= (1.f / NEXP); ml *= (1.f / NEXP);
        float vi = 0.f, vl = 0.f;
        for (int q = 0; q < NEXP; ++q) {
            float di = pimp[0][q] - mi, dl = pld[0][q] - ml;
            vi += di * di; vl += dl * dl;
        }
        vi *= (1.f / NEXP); vl *= (1.f / NEXP);
        out[5 * N_TOKENS] = 0.1f * (vi / (mi * mi + EPS)) + 0.1f * (vl / (ml * ml + EPS));
    }
}

extern "C" void kernel_launch(void* const* d_in, const int* in_sizes, int n_in,
                              void* d_out, int out_size)
{
    const float* x     = (const float*)d_in[0];
    const float* noise = (const float*)d_in[1];
    const float* Wg    = (const float*)d_in[2];
    const float* Wn    = (const float*)d_in[3];
    float* out = (float*)d_out;

    cudaFuncSetAttribute(router_main_kernel,
                         cudaFuncAttributeMaxDynamicSharedMemorySize, SMEM_BYTES);
    wpack_kernel<<<128, 256>>>(Wg, Wn);
    router_main_kernel<<<NBLOCKS, NTHREADS, SMEM_BYTES>>>(x, noise, out);
    router_fixup_kernel<<<128, 256>>>(x, noise, Wg, Wn, out);
    router_finalize_kernel<<<1, 512>>>(out);
}

// round 8
// speedup vs baseline: 2.0939x; 1.4686x over previous
#include <cuda_runtime.h>
#include <cuda_fp16.h>
#include <math_constants.h>
#include <cstdint>

#define N_TOKENS   16384
#define DIM        2048
#define NEXP       64
#define NCOLS      128
#define TOK_BLK    128
#define NBLOCKS    (N_TOKENS / TOK_BLK)   // 128
#define NTHREADS   512
#define KC         64
#define NCHUNK     (DIM / KC)             // 32
#define EPS        1e-9f
#define WINDOW     0.05f                  // candidate window below approx v3

#define PADB       144
#define TILE_BYTES (128 * PADB)           // 18432
#define A_HI       0
#define B_HI       TILE_BYTES
#define ST_SIZE    (2 * TILE_BYTES)       // 36864
#define B_CHUNK_U16X (TILE_BYTES / 16)    // 1152

// epilogue smem (floats): LOGI[128][129] + VT[128][65] + small arrays
#define EPI_FLOATS (128*129 + 128*65 + 4*128 + 8*64 + 64)
#define SMEM_BYTES (1024 + ((2*ST_SIZE > EPI_FLOATS*4) ? 2*ST_SIZE : EPI_FLOATS*4))

// ---- static device scratch ----
__device__ uint4    g_wpack[NCHUNK * B_CHUNK_U16X];   // 576KB fp16 W, padded chunks
__device__ float    g_imp_part [NBLOCKS * NEXP];
__device__ float    g_load_part[NBLOCKS * NEXP];
__device__ unsigned long long g_mask[N_TOKENS];

// ======================= helpers =======================
__device__ __forceinline__ uint32_t smem_u32(const void* p) {
    uint32_t a;
    asm("{ .reg .u64 t; cvta.to.shared.u64 t, %1; cvt.u32.u64 %0, t; }" : "=r"(a) : "l"(p));
    return a;
}
__device__ __forceinline__ void ldsm_x4(uint32_t (&r)[4], uint32_t addr) {
    asm volatile("ldmatrix.sync.aligned.m8n8.x4.shared.b16 {%0,%1,%2,%3}, [%4];"
                 : "=r"(r[0]), "=r"(r[1]), "=r"(r[2]), "=r"(r[3]) : "r"(addr));
}
__device__ __forceinline__ void mma16816h(float* d, const uint32_t* a, uint32_t b0, uint32_t b1) {
    asm volatile("mma.sync.aligned.m16n8k16.row.col.f32.f16.f16.f32 "
                 "{%0,%1,%2,%3}, {%4,%5,%6,%7}, {%8,%9}, {%0,%1,%2,%3};"
                 : "+f"(d[0]), "+f"(d[1]), "+f"(d[2]), "+f"(d[3])
                 : "r"(a[0]), "r"(a[1]), "r"(a[2]), "r"(a[3]), "r"(b0), "r"(b1));
}
#define CP_ASYNC16(dst, src) \
    asm volatile("cp.async.cg.shared.global [%0], [%1], 16;" :: "r"(dst), "l"(src))
#define CP_COMMIT()  asm volatile("cp.async.commit_group;")
#define CP_WAIT0()   asm volatile("cp.async.wait_group 0;")

__device__ __forceinline__ uint4 cvt8h(float4 a, float4 b) {
    __half2 h0 = __floats2half2_rn(a.x, a.y);
    __half2 h1 = __floats2half2_rn(a.z, a.w);
    __half2 h2 = __floats2half2_rn(b.x, b.y);
    __half2 h3 = __floats2half2_rn(b.z, b.w);
    uint4 r;
    r.x = *reinterpret_cast<uint32_t*>(&h0);
    r.y = *reinterpret_cast<uint32_t*>(&h1);
    r.z = *reinterpret_cast<uint32_t*>(&h2);
    r.w = *reinterpret_cast<uint32_t*>(&h3);
    return r;
}

// ======================= W precompute (fp16, padded chunks) =======================
__global__ void __launch_bounds__(256) wpack_kernel(const float* __restrict__ Wg,
                                                    const float* __restrict__ Wn) {
    int id = blockIdx.x * 256 + threadIdx.x;     // 32768 = 32 chunks * 128 cols * 8 units
    int chunk = id >> 10;
    int rem   = id & 1023;
    int col = rem >> 3, u = rem & 7;
    const float* src = (col < NEXP ? Wg + (size_t)col * DIM : Wn + (size_t)(col - NEXP) * DIM)
                       + chunk * KC + u * 8;
    float4 a = ((const float4*)src)[0];
    float4 b = ((const float4*)src)[1];
    char* base = (char*)g_wpack + (size_t)chunk * TILE_BYTES;
    *(uint4*)(base + col * PADB + u * 16) = cvt8h(a, b);
}

// ======================= main: fp16 1-pass GEMM + approx epilogue =======================
__global__ void __launch_bounds__(NTHREADS)
router_main_kernel(const float* __restrict__ x,
                   const float* __restrict__ noise)
{
    extern __shared__ char sm[];
    const uint32_t smb = smem_u32(sm);
    const uint32_t stb = (smb + 1023u) & ~1023u;
    char* st_ptr = sm + (stb - smb);

    const int tid  = threadIdx.x;
    const int wid  = tid >> 5;           // 0..15
    const int lane = tid & 31;
    const int wm   = wid >> 1;           // 0..7  (16 rows)
    const int wn   = wid & 1;            // 0..1  (64 cols)
    const int tok0 = blockIdx.x * TOK_BLK;

    const int arow = tid >> 3, au = tid & 7;   // A-stage: idx = tid + t*512

    float acc[8][4];
#pragma unroll
    for (int j = 0; j < 8; ++j)
#pragma unroll
        for (int q = 0; q < 4; ++q) acc[j][q] = 0.f;

    // ---- prologue: stage chunk 0 ----
    {
        const uint4* src = g_wpack;
        uint32_t d = stb + B_HI;
#pragma unroll
        for (int t = 0; t < 3; ++t) {
            int idx = tid + t * 512;
            if (idx < B_CHUNK_U16X) CP_ASYNC16(d + idx * 16, src + idx);
        }
        CP_COMMIT();

        float4 ar[4];
#pragma unroll
        for (int t = 0; t < 2; ++t) {
            const float4* p = (const float4*)(x + (size_t)(tok0 + arow + t * 64) * DIM + au * 8);
            ar[2*t]   = p[0];
            ar[2*t+1] = p[1];
        }
#pragma unroll
        for (int t = 0; t < 2; ++t) {
            int r = arow + t * 64;
            *(uint4*)(st_ptr + A_HI + r * PADB + au * 16) = cvt8h(ar[2*t], ar[2*t+1]);
        }
        CP_WAIT0();
        __syncthreads();
    }

    const uint32_t a_lane = (uint32_t)((wm * 16 + (lane & 15)) * PADB + (lane >> 4) * 16);
    const uint32_t b_lane = (uint32_t)((wn * 64 + (lane & 15)) * PADB + (lane >> 4) * 16);

    for (int c = 0; c < NCHUNK; ++c) {
        const int buf = c & 1;
        const uint32_t sb = stb + buf * ST_SIZE;
        const bool pf = (c + 1 < NCHUNK);
        char* stn = st_ptr + (buf ^ 1) * ST_SIZE;

        float4 ar[4];
        if (pf) {
            const uint4* src = g_wpack + (size_t)(c + 1) * B_CHUNK_U16X;
            uint32_t d = stb + (buf ^ 1) * ST_SIZE + B_HI;
#pragma unroll
            for (int t = 0; t < 3; ++t) {
                int idx = tid + t * 512;
                if (idx < B_CHUNK_U16X) CP_ASYNC16(d + idx * 16, src + idx);
            }
            CP_COMMIT();
            const int koff = (c + 1) * KC;
#pragma unroll
            for (int t = 0; t < 2; ++t) {
                const float4* p = (const float4*)(x + (size_t)(tok0 + arow + t * 64) * DIM + koff + au * 8);
                ar[2*t]   = p[0];
                ar[2*t+1] = p[1];
            }
        }

        // ---- MMA over chunk c: single fp16 pass ----
#pragma unroll
        for (int ks = 0; ks < 4; ++ks) {
            const uint32_t ko = ks * 32;
            uint32_t ah[4];
            ldsm_x4(ah, sb + A_HI + a_lane + ko);
            uint32_t bh[4][4];
#pragma unroll
            for (int p = 0; p < 4; ++p)
                ldsm_x4(bh[p], sb + B_HI + b_lane + p * 16 * PADB + ko);
#pragma unroll
            for (int p = 0; p < 4; ++p)
#pragma unroll
                for (int h = 0; h < 2; ++h)
                    mma16816h(acc[2 * p + h], ah, bh[p][h], bh[p][2 + h]);
        }

        if (pf) {
#pragma unroll
            for (int t = 0; t < 2; ++t) {
                int r = arow + t * 64;
                *(uint4*)(stn + A_HI + r * PADB + au * 16) = cvt8h(ar[2*t], ar[2*t+1]);
            }
            CP_WAIT0();
        }
        __syncthreads();
    }

    // ---------------- epilogue (overlay) ----------------
    float* smf = (float*)st_ptr;
    const int LSTR = 129;
    const int LOGI = 0;                       // [128][129]: 0-63 gate, 64-127 noise->sd
    const int VT   = 128 * 129, VSTR = 65;    // [128][65] approx noisy logits
    const int V2O  = VT + 128 * 65;
    const int V3O  = V2O + 128;
    const int I1O  = V3O + 128, I2O = I1O + 128;
    const int LDO  = I2O + 128;               // [8][64]

#pragma unroll
    for (int nt = 0; nt < 8; ++nt)
#pragma unroll
        for (int ci = 0; ci < 4; ++ci) {
            int row = wm * 16 + (lane >> 2) + (ci >> 1) * 8;
            int col = wn * 64 + nt * 8 + (lane & 3) * 2 + (ci & 1);
            smf[LOGI + row * LSTR + col] = acc[nt][ci];
        }
    __syncthreads();

    // E1: one thread per token — softplus, approx noisy logits, top-3, candidate mask
    if (tid < TOK_BLK) {
        const int t = tid;
        const float* nrow = noise + (size_t)(tok0 + t) * NEXP;
        float v1 = -CUDART_INF_F, v2 = -CUDART_INF_F, v3 = -CUDART_INF_F;
        int i1 = 0, i2 = 0;
#pragma unroll 4
        for (int e = 0; e < NEXP; ++e) {
            float lg = smf[LOGI + t * LSTR + e];
            float nl = smf[LOGI + t * LSTR + NEXP + e];
            float sp = fmaxf(nl, 0.f) + log1pf(expf(-fabsf(nl)));
            float sd = sp + EPS;
            smf[LOGI + t * LSTR + NEXP + e] = sd;       // overwrite with noise_std
            float nz = fmaf(nrow[e], sd, lg);
            smf[VT + t * VSTR + e] = nz;
            if (nz > v1)      { v3 = v2; v2 = v1; i2 = i1; v1 = nz; i1 = e; }
            else if (nz > v2) { v3 = v2; v2 = nz; i2 = e; }
            else if (nz > v3) { v3 = nz; }
        }
        unsigned long long m = 0ull;
        float thr = v3 - WINDOW;
#pragma unroll 4
        for (int e = 0; e < NEXP; ++e)
            m |= (unsigned long long)(smf[VT + t * VSTR + e] >= thr) << e;
        g_mask[tok0 + t] = m;
        smf[V2O + t] = v2; smf[V3O + t] = v3;
        ((int*)(smf + I1O))[t] = i1; ((int*)(smf + I2O))[t] = i2;
    }
    __syncthreads();

    // E2: load partials (smooth in all approx quantities)
    {
        const int e = tid & 63, g = tid >> 6;   // 8 groups x 16 tokens
        float ld = 0.f;
#pragma unroll 4
        for (int t = g * 16; t < g * 16 + 16; ++t) {
            int ii1 = ((int*)(smf + I1O))[t], ii2 = ((int*)(smf + I2O))[t];
            bool intop = (ii1 == e) || (ii2 == e);
            float kth = intop ? smf[V3O + t] : smf[V2O + t];
            float sd  = smf[LOGI + t * LSTR + NEXP + e];
            float lg  = smf[LOGI + t * LSTR + e];
            float z   = (lg - kth) / (sd + EPS);
            ld += 0.5f * (1.f + erff(z * 0.70710678118654752f));
        }
        smf[LDO + g * 64 + e] = ld;
    }
    __syncthreads();

    if (tid < NEXP) {
        float sl = 0.f;
#pragma unroll
        for (int g = 0; g < 8; ++g) sl += smf[LDO + g * 64 + tid];
        g_load_part[blockIdx.x * NEXP + tid] = sl;
    }
}

// ======================= refine: exact fp32 dots for candidates, all tokens =======================
__global__ void __launch_bounds__(512)
router_refine_kernel(const float* __restrict__ x, const float* __restrict__ noise,
                     const float* __restrict__ Wg, const float* __restrict__ Wn,
                     float* __restrict__ out)
{
    __shared__ float w1s[TOK_BLK], w2s[TOK_BLK];
    __shared__ int   i1s[TOK_BLK], i2s[TOK_BLK];
    const int tid  = threadIdx.x;
    const int wid  = tid >> 5;           // 0..15
    const int lane = tid & 31;
    const int tok0 = blockIdx.x * TOK_BLK;

    for (int tl = wid; tl < TOK_BLK; tl += 16) {
        const int t = tok0 + tl;
        unsigned long long m = g_mask[t];
        const float* xrow = x + (size_t)t * DIM;
        float v1 = -CUDART_INF_F, v2 = -CUDART_INF_F;
        int i1 = 0, i2 = 0;

        while (m) {
            int e = __ffsll((long long)m) - 1;
            m &= m - 1;
            const float* wg = Wg + (size_t)e * DIM;
            const float* wn = Wn + (size_t)e * DIM;
            float sg = 0.f, sn = 0.f;
#pragma unroll
            for (int j = 0; j < 16; ++j) {
                int k = lane * 4 + j * 128;
                float4 xv = *(const float4*)(xrow + k);
                float4 g4 = *(const float4*)(wg + k);
                float4 n4 = *(const float4*)(wn + k);
                sg = fmaf(xv.x, g4.x, fmaf(xv.y, g4.y, fmaf(xv.z, g4.z, fmaf(xv.w, g4.w, sg))));
                sn = fmaf(xv.x, n4.x, fmaf(xv.y, n4.y, fmaf(xv.z, n4.z, fmaf(xv.w, n4.w, sn))));
            }
#pragma unroll
            for (int o = 16; o > 0; o >>= 1) {
                sg += __shfl_xor_sync(0xFFFFFFFFu, sg, o);
                sn += __shfl_xor_sync(0xFFFFFFFFu, sn, o);
            }
            float sp = fmaxf(sn, 0.f) + log1pf(expf(-fabsf(sn)));
            float sd = sp + EPS;
            float nz = fmaf(noise[(size_t)t * NEXP + e], sd, sg);
            if (nz > v1)      { v2 = v1; i2 = i1; v1 = nz; i1 = e; }
            else if (nz > v2) { v2 = nz; i2 = e; }
        }

        if (lane == 0) {
            float ed  = expf(v2 - v1);
            float inv = 1.f / (1.f + ed);
            float w1 = inv, w2 = ed * inv;
            out[2 * t]                    = (float)i1;
            out[2 * t + 1]                = (float)i2;
            out[2 * N_TOKENS + 2 * t]     = w1;
            out[2 * N_TOKENS + 2 * t + 1] = w2;
            out[4 * N_TOKENS + t]         = w1;
            w1s[tl] = w1; w2s[tl] = w2; i1s[tl] = i1; i2s[tl] = i2;
        }
    }
    __syncthreads();

    // importance partials (exact), deterministic per block
    if (tid < NEXP) {
        float imp = 0.f;
#pragma unroll 4
        for (int tl = 0; tl < TOK_BLK; ++tl) {
            if (i1s[tl] == tid) imp += w1s[tl];
            if (i2s[tl] == tid) imp += w2s[tl];
        }
        g_imp_part[blockIdx.x * NEXP + tid] = imp;
    }
}

// ======================= finalize =======================
__global__ void __launch_bounds__(512) router_finalize_kernel(float* __restrict__ out)
{
    __shared__ float pimp[8][64], pld[8][64];
    const int tid = threadIdx.x;
    const int e = tid & 63, g = tid >> 6;
    float si = 0.f, sl = 0.f;
#pragma unroll
    for (int b = g; b < NBLOCKS; b += 8) {
        si += g_imp_part [b * NEXP + e];
        sl += g_load_part[b * NEXP + e];
    }
    pimp[g][e] = si; pld[g][e] = sl;
    __syncthreads();
    if (tid < 64) {
        float a = 0.f, b = 0.f;
#pragma unroll
        for (int q = 0; q < 8; ++q) { a += pimp[q][tid]; b += pld[q][tid]; }
        pimp[0][tid] = a; pld[0][tid] = b;
    }
    __syncthreads();
    if (tid == 0) {
        float mi = 0.f, ml = 0.f;
        for (int q = 0; q < NEXP; ++q) { mi += pimp[0][q]; ml += pld[0][q]; }
        mi *= (1.f / NEXP); ml *= (1.f / NEXP);
        float vi = 0.f, vl = 0.f;
        for (int q = 0; q < NEXP; ++q) {
            float di = pimp[0][q] - mi, dl = pld[0][q] - ml;
            vi += di * di; vl += dl * dl;
        }
        vi *= (1.f / NEXP); vl *= (1.f / NEXP);
        out[5 * N_TOKENS] = 0.1f * (vi / (mi * mi + EPS)) + 0.1f * (vl / (ml * ml + EPS));
    }
}

extern "C" void kernel_launch(void* const* d_in, const int* in_sizes, int n_in,
                              void* d_out, int out_size)
{
    const float* x     = (const float*)d_in[0];
    const float* noise = (const float*)d_in[1];
    const float* Wg    = (const float*)d_in[2];
    const float* Wn    = (const float*)d_in[3];
    float* out = (float*)d_out;

    cudaFuncSetAttribute(router_main_kernel,
                         cudaFuncAttributeMaxDynamicSharedMemorySize, SMEM_BYTES);
    wpack_kernel<<<128, 256>>>(Wg, Wn);
    router_main_kernel<<<NBLOCKS, NTHREADS, SMEM_BYTES>>>(x, noise);
    router_refine_kernel<<<NBLOCKS, 512>>>(x, noise, Wg, Wn, out);
    router_finalize_kernel<<<1, 512>>>(out);
}